// round 3
// baseline (speedup 1.0000x reference)
#include <cuda_runtime.h>

// ConvCaps (matrix capsule conv + EM routing), fully fused, f32x2-packed.
// Grid: 576 CTAs (one per (n, oi, oj) output position). Block: 256 threads (8 warps),
// capped at 128 regs (__launch_bounds__(256,2)) for 2 CTAs/SM.
// lane <-> output capsule o (O=32). Each warp strides over k in [0,288), unroll x2.
// Votes recomputed per pass (3 passes) from pose (smem) and W (L2), never stored.
// All D=16-dimension math runs as packed f32x2 (FFMA2/FMUL2/FADD2), 2x fp32 rate.

#define KTOT 288
#define PDIM 6
#define NTHREADS 256
#define NWARPS 8
#define KITERS (KTOT / NWARPS)   // 36 (even)
#define EPSV 1e-9f

typedef unsigned long long u64;

__device__ __forceinline__ u64 pack2(float lo, float hi) {
    u64 r; asm("mov.b64 %0, {%1, %2};" : "=l"(r) : "f"(lo), "f"(hi)); return r;
}
__device__ __forceinline__ u64 bcast2(float x) { return pack2(x, x); }
__device__ __forceinline__ void unpack2(u64 v, float& lo, float& hi) {
    asm("mov.b64 {%0, %1}, %2;" : "=f"(lo), "=f"(hi) : "l"(v));
}
__device__ __forceinline__ u64 fma2(u64 a, u64 b, u64 c) {
    u64 d; asm("fma.rn.f32x2 %0, %1, %2, %3;" : "=l"(d) : "l"(a), "l"(b), "l"(c)); return d;
}
__device__ __forceinline__ u64 mul2(u64 a, u64 b) {
    u64 d; asm("mul.rn.f32x2 %0, %1, %2;" : "=l"(d) : "l"(a), "l"(b)); return d;
}
__device__ __forceinline__ u64 add2(u64 a, u64 b) {
    u64 d; asm("add.rn.f32x2 %0, %1, %2;" : "=l"(d) : "l"(a), "l"(b)); return d;
}

__device__ __forceinline__ float warpMax(float v) {
#pragma unroll
    for (int s = 16; s; s >>= 1) v = fmaxf(v, __shfl_xor_sync(0xffffffffu, v, s));
    return v;
}
__device__ __forceinline__ float warpSum(float v) {
#pragma unroll
    for (int s = 16; s; s >>= 1) v += __shfl_xor_sync(0xffffffffu, v, s);
    return v;
}

// W(k, o=lane): 16 contiguous floats via 2x LDG.128-pair; u64 halves are the
// packed (n, n+1) column pairs directly.
__device__ __forceinline__ void loadW(u64* W2, const float* __restrict__ w_g,
                                      int k, int lane) {
    const ulonglong2* wp = (const ulonglong2*)(w_g + ((size_t)k * 32 + lane) * 16);
    ulonglong2 q0 = wp[0], q1 = wp[1], q2 = wp[2], q3 = wp[3];
    W2[0] = q0.x; W2[1] = q0.y; W2[2] = q1.x; W2[3] = q1.y;
    W2[4] = q2.x; W2[5] = q2.y; W2[6] = q3.x; W2[7] = q3.y;
}

struct EmState {
    u64 negmu2[8], isig2[8];
    float logc, loga;
};

// One k's worth of work: votes -> (r) -> moment accumulation.
__device__ __forceinline__ void processK(
    const u64* __restrict__ W2, const float* __restrict__ ps, float aink,
    int pass, const EmState& st,
    float& S0, u64* __restrict__ S1_2, u64* __restrict__ S2_2)
{
    // votes V = P(4x4) @ W(4x4); v2[m*2+h] = packed (d = 4m+2h, 4m+2h+1)
    u64 v2[8];
#pragma unroll
    for (int m = 0; m < 4; m++) {
        u64 p0 = bcast2(ps[m * 4 + 0]);
        u64 p1 = bcast2(ps[m * 4 + 1]);
        u64 p2 = bcast2(ps[m * 4 + 2]);
        u64 p3 = bcast2(ps[m * 4 + 3]);
        u64 a0 = mul2(p0, W2[0]);
        u64 a1 = mul2(p0, W2[1]);
        a0 = fma2(p1, W2[2], a0);
        a1 = fma2(p1, W2[3], a1);
        a0 = fma2(p2, W2[4], a0);
        a1 = fma2(p2, W2[5], a1);
        v2[m * 2 + 0] = fma2(p3, W2[6], a0);
        v2[m * 2 + 1] = fma2(p3, W2[7], a1);
    }

    float rw;
    if (pass == 0) {
        rw = aink * (1.f / 32.f);
    } else {
        // E-step: log_p, then softmax over o (= lanes)
        u64 qd2 = bcast2(0.f);
#pragma unroll
        for (int j = 0; j < 8; j++) {
            u64 df = add2(v2[j], st.negmu2[j]);
            qd2 = fma2(mul2(df, df), st.isig2[j], qd2);
        }
        float qlo, qhi; unpack2(qd2, qlo, qhi);
        float logit = st.loga - 0.5f * (st.logc + qlo + qhi);
        float mx = warpMax(logit);
        float e = __expf(logit - mx);
        float s = warpSum(e);
        rw = (e / s) * aink;
    }

    S0 += rw;
    u64 rw2 = bcast2(rw);
#pragma unroll
    for (int j = 0; j < 8; j++) {
        S1_2[j] = fma2(rw2, v2[j], S1_2[j]);
        S2_2[j] = fma2(mul2(rw2, v2[j]), v2[j], S2_2[j]);
    }
}

__global__ __launch_bounds__(NTHREADS, 2)
void convcaps_kernel(const float* __restrict__ pose_g,
                     const float* __restrict__ act_g,
                     const float* __restrict__ w_g,
                     const float* __restrict__ beta_v,
                     const float* __restrict__ beta_a,
                     float* __restrict__ out) {
    __shared__ float pose_s[KTOT * 16];
    __shared__ float act_s[KTOT];
    __shared__ float acc[33 * 32];        // S0 | S1[16] | S2[16], per o
    __shared__ float mu_s[16 * 32];       // [d][o]
    __shared__ float isig_s[16 * 32];     // [d][o]
    __shared__ float logc_s[32];
    __shared__ float loga_s[32];

    const int b   = blockIdx.x;
    const int n   = b / (PDIM * PDIM);
    const int rem = b % (PDIM * PDIM);
    const int oi  = rem / PDIM;
    const int oj  = rem % PDIM;
    const int tid  = threadIdx.x;
    const int wid  = tid >> 5;
    const int lane = tid & 31;

    // ---- im2col gather into smem ----
    // pose: (16,14,14,32,16); each (ki,kj) block = 512 contiguous floats (c,d)
    for (int q = tid; q < 9 * 128; q += NTHREADS) {
        int blk = q >> 7, off = q & 127;
        int ki = blk / 3, kj = blk - 3 * ki;
        const float4* src = (const float4*)(pose_g
            + ((size_t)n * 14 + (2 * oi + ki)) * 14 * 512
            + (size_t)(2 * oj + kj) * 512);
        ((float4*)pose_s)[blk * 128 + off] = src[off];
    }
    // act: (16,14,14,32,1); each (ki,kj) block = 32 contiguous floats
    for (int q = tid; q < KTOT; q += NTHREADS) {
        int blk = q >> 5, c = q & 31;
        int ki = blk / 3, kj = blk - 3 * ki;
        act_s[q] = act_g[((size_t)n * 14 + (2 * oi + ki)) * 14 * 32
                         + (size_t)(2 * oj + kj) * 32 + c];
    }

    EmState st;
    st.logc = 0.f; st.loga = 0.f;
    const float inv_temp[3] = {0.0005f, 0.000975f, 0.00142625f};
    const float LOG2PI = 1.8378770664093453f;

    for (int pass = 0; pass < 3; ++pass) {
        for (int q = tid; q < 33 * 32; q += NTHREADS) acc[q] = 0.f;
        __syncthreads();

        float S0 = 0.f;
        u64 S1_2[8], S2_2[8];
        const u64 Z = bcast2(0.f);
#pragma unroll
        for (int j = 0; j < 8; j++) { S1_2[j] = Z; S2_2[j] = Z; }

        // k loop, unrolled x2: both W tiles load up front (MLP=8 LDG.128)
        for (int i = 0; i < KITERS; i += 2) {
            const int k0 = wid + i * NWARPS;
            const int k1 = k0 + NWARPS;
            u64 Wa[8], Wb[8];
            loadW(Wa, w_g, k0, lane);
            loadW(Wb, w_g, k1, lane);
            processK(Wa, pose_s + k0 * 16, act_s[k0], pass, st, S0, S1_2, S2_2);
            processK(Wb, pose_s + k1 * 16, act_s[k1], pass, st, S0, S1_2, S2_2);
        }

        // cross-warp reduction into smem (lane-spread addresses: conflict-free)
        atomicAdd(&acc[lane], S0);
#pragma unroll
        for (int j = 0; j < 8; j++) {
            float lo, hi;
            unpack2(S1_2[j], lo, hi);
            atomicAdd(&acc[(1 + 2 * j) * 32 + lane], lo);
            atomicAdd(&acc[(2 + 2 * j) * 32 + lane], hi);
            unpack2(S2_2[j], lo, hi);
            atomicAdd(&acc[(17 + 2 * j) * 32 + lane], lo);
            atomicAdd(&acc[(18 + 2 * j) * 32 + lane], hi);
        }
        __syncthreads();

        // ---- M-step statistics (warp 0, lane = o) ----
        if (wid == 0) {
            const int o = lane;
            float S0t  = acc[o];
            float R    = S0t + EPSV;
            float invR = 1.f / R;
            float bv   = beta_v[o];
            float csum = 0.f, lcn = 0.f;
#pragma unroll
            for (int d = 0; d < 16; d++) {
                float s1 = acc[(1 + d) * 32 + o];
                float s2 = acc[(17 + d) * 32 + o];
                float m_ = s1 * invR;
                // sum rw (v-mu)^2 = S2 - mu*(2*S1 - mu*S0)
                float sg = (s2 - m_ * (2.f * s1 - m_ * S0t)) * invR + EPSV;
                mu_s[d * 32 + o]   = m_;
                isig_s[d * 32 + o] = 1.f / sg;
                float lg = __logf(sg);
                lcn  += lg;
                csum += bv + 0.5f * lg;
                if (pass == 2) out[((size_t)b * 32 + o) * 16 + d] = m_;
            }
            float x = inv_temp[pass] * (beta_a[o] - csum * R);
            float aout = 1.f / (1.f + __expf(-x));
            logc_s[o] = lcn + 16.f * LOG2PI;     // sum_d log(2*pi*sigma2)
            loga_s[o] = __logf(aout + EPSV);
            if (pass == 2) out[576 * 512 + (size_t)b * 32 + o] = aout;
        }
        __syncthreads();

        if (pass < 2) {
#pragma unroll
            for (int j = 0; j < 8; j++) {
                st.negmu2[j] = pack2(-mu_s[(2 * j) * 32 + lane],
                                     -mu_s[(2 * j + 1) * 32 + lane]);
                st.isig2[j]  = pack2(isig_s[(2 * j) * 32 + lane],
                                     isig_s[(2 * j + 1) * 32 + lane]);
            }
            st.logc = logc_s[lane];
            st.loga = loga_s[lane];
        }
    }
}

extern "C" void kernel_launch(void* const* d_in, const int* in_sizes, int n_in,
                              void* d_out, int out_size) {
    const float* pose = (const float*)d_in[0];
    const float* act  = (const float*)d_in[1];
    const float* w    = (const float*)d_in[2];
    const float* bv   = (const float*)d_in[3];
    const float* ba   = (const float*)d_in[4];
    (void)in_sizes; (void)n_in; (void)out_size;
    convcaps_kernel<<<576, NTHREADS>>>(pose, act, w, bv, ba, (float*)d_out);
}